// round 14
// baseline (speedup 1.0000x reference)
#include <cuda_runtime.h>
#include <cuda_fp16.h>
#include <cstdint>

// ---------------- problem constants ----------------
#define B_TOT   16384
#define T_HOR   128
#define F_IN    29
#define K_HID   512
#define BTILE   64
#define NTH     256
#define NCTAS   (B_TOT / BTILE)     // 256
#define TF_STR  (T_HOR * F_IN)      // 3712 floats per batch row

// pair-shared X stage: 16 rows x 15 f16x2 pairs, stride 20 u32 (conflict-free), dbl-buffered
#define XSTRIDE 20                  // u32 stride per row
#define XPAIRU  (16 * XSTRIDE)      // 320 u32 per buffer

// ---------------- shared memory layout ----------------
#define SM_B4_OFF   0                               // 64 nt x 32 lanes x uint4 = 32KB
#define SM_B1_OFF   32768                           // 256 u32 (b1 f16x2 pairs) = 1KB
#define SM_W2_OFF   (SM_B1_OFF + 1024)              // 33792: 128 x uint2 (w2 f16x2) = 1KB
#define SM_PART_OFF (SM_W2_OFF + 1024)              // 34816: 2 x 128 floats = 1KB
#define SM_X_OFF    (SM_PART_OFF + 1024)            // 35840: 4 pairs x 2 x 320 u32 = 10240B
#define SM_TOTAL    (SM_X_OFF + 4 * 2 * XPAIRU * 4) // 46080 bytes (2 CTAs/SM)

static __device__ __forceinline__ uint32_t h2u(float lo, float hi) {
    uint32_t r;
    asm("cvt.rn.f16x2.f32 %0, %1, %2;" : "=r"(r) : "f"(hi), "f"(lo));
    return r;
}

// packed fp16 tanh: one MUFU op for 2 elements
static __device__ __forceinline__ uint32_t tanh2(uint32_t z) {
    uint32_t h;
    asm("tanh.approx.f16x2 %0, %1;" : "=r"(h) : "r"(z));
    return h;
}

// fp16-accumulator MMA m16n8k16: D,C are 2 f16x2 regs (row lg | row lg+8)
#define MMA_F16A(d01, d23, a0, a1, a2, a3, b0, b1)                             \
    asm("mma.sync.aligned.m16n8k16.row.col.f16.f16.f16.f16 "                   \
        "{%0,%1}, {%2,%3,%4,%5}, {%6,%7}, {%0,%1};"                             \
        : "+r"(d01), "+r"(d23)                                                  \
        : "r"(a0), "r"(a1), "r"(a2), "r"(a3), "r"(b0), "r"(b1))

// fp32-accumulator MMA (dot with W2)
#define MMA_F16(d0, d1, d2, d3, a0, a1, a2, a3, b0, b1)                        \
    asm("mma.sync.aligned.m16n8k16.row.col.f32.f16.f16.f32 "                   \
        "{%0,%1,%2,%3}, {%4,%5,%6,%7}, {%8,%9}, {%0,%1,%2,%3};"                \
        : "+f"(d0), "+f"(d1), "+f"(d2), "+f"(d3)                               \
        : "r"(a0), "r"(a1), "r"(a2), "r"(a3), "r"(b0), "r"(b1))

// pairwise named barrier: 2 warps = 64 threads
#define BAR_PAIR(id) asm volatile("bar.sync %0, 64;" :: "r"(id) : "memory")

__global__ void __launch_bounds__(NTH, 2)
narx_kernel(const float* __restrict__ X, const float* __restrict__ y0,
            const float* __restrict__ W1, const float* __restrict__ b1,
            const float* __restrict__ W2, const float* __restrict__ b2,
            float* __restrict__ out)
{
    extern __shared__ char smem[];
    uint4*    __restrict__ B4   = (uint4*)(smem + SM_B4_OFF);
    uint32_t* __restrict__ b1h  = (uint32_t*)(smem + SM_B1_OFF);
    uint2*    __restrict__ w2sm = (uint2*)(smem + SM_W2_OFF);
    float*    __restrict__ part = (float*)(smem + SM_PART_OFF);

    const int tid  = threadIdx.x;
    const int w    = tid >> 5;
    const int lane = tid & 31;
    const int lq   = lane & 3;       // quad lane
    const int lg   = lane >> 2;      // group (row selector 0..7)
    const int pr   = w >> 1;         // pair index 0..3
    const int h    = w & 1;          // column half: cols h*256 .. h*256+255
    const int ctaB0 = blockIdx.x * BTILE;

    uint32_t* __restrict__ Xpair = (uint32_t*)(smem + SM_X_OFF) + pr * (2 * XPAIRU);

    // --- stage B (W1, all 32 rows) as fp16 ---
    for (int idx = tid; idx < 2048; idx += NTH) {
        const int lnt = idx & 31;
        const int col = (idx >> 5) * 8 + (lnt >> 2);
        const int kk = (lnt & 3) * 2;
        uint4 bv;
        bv.x = h2u(W1[kk * K_HID + col],        W1[(kk + 1) * K_HID + col]);
        bv.y = h2u(W1[(kk + 8) * K_HID + col],  W1[(kk + 9) * K_HID + col]);
        bv.z = h2u(W1[(kk + 16) * K_HID + col], W1[(kk + 17) * K_HID + col]);
        bv.w = h2u(W1[(kk + 24) * K_HID + col], W1[(kk + 25) * K_HID + col]);
        B4[idx] = bv;
    }
    // --- b1 as f16x2 col-pairs: b1h[ntg*4+lq] = (b1[c0], b1[c1]) ---
    for (int p = tid; p < K_HID / 2; p += NTH)
        b1h[p] = h2u(b1[2 * p], b1[2 * p + 1]);
    // --- W2 as f16x2 B-fragments for the dot-MMA ---
    for (int idx = tid; idx < 128; idx += NTH) {
        const int lqt = idx & 3, ntp = (idx >> 2) & 15, hh = idx >> 6;
        const int C = (hh * 32 + 2 * ntp) * 8;
        uint2 v;
        v.x = h2u(W2[C + 2 * lqt],     W2[C + 2 * lqt + 1]);
        v.y = h2u(W2[C + 2 * lqt + 8], W2[C + 2 * lqt + 9]);
        w2sm[idx] = v;
    }

    // --- X staging (packed f16x2): pair covers 16 rows x 15 pairs = 240 u32,
    //     warp h stages elements [h*120, h*120+120) ---
    const float* __restrict__ Xbase = X + (size_t)(ctaB0 + pr * 16) * TF_STR;
    const int jBase = h * 120;

    #pragma unroll
    for (int k = 0; k < 4; ++k) {
        if (lane + k * 32 < 120) {
            const int j = jBase + lane + k * 32;
            const int row = j / 15, p = j - row * 15;
            const float* src = Xbase + (size_t)row * TF_STR;
            const float lo = __ldg(src + 2 * p);
            const float hi = (p < 14) ? __ldg(src + 2 * p + 1) : 0.0f;
            Xpair[row * XSTRIDE + p] = h2u(lo, hi);
        }
    }
    __syncthreads();

    // --- per-thread rows: rowG (lg) and rowG+8 ---
    const int rowG = ctaB0 + pr * 16 + lg;
    float* __restrict__ outA = out + (size_t)rowG * T_HOR;
    float* __restrict__ outB = outA + 8 * T_HOR;

    const float b2v = b2[0];
    const int barId = 1 + pr;
    const int pBase = pr * 32;

    float f0a = y0[rowG * 3 + 0],       f1a = y0[rowG * 3 + 1],       f2a = y0[rowG * 3 + 2];
    float f0b = y0[(rowG + 8) * 3 + 0], f1b = y0[(rowG + 8) * 3 + 1], f2b = y0[(rowG + 8) * 3 + 2];
    // packed feedback: fb0 in HIGH half (pairs with x28 lo); (fb1,fb2) full pair
    uint32_t fb0aH = h2u(0.0f, f0a), fb0bH = h2u(0.0f, f0b);
    uint32_t fb12a = h2u(f1a, f2a),  fb12b = h2u(f1b, f2b);

    const int ntOfs = h * 32;            // this warp's 32 n-tiles (256 cols)
    const int w2Base = h * 64;

    for (int t = 0; t < T_HOR; ++t) {
        const uint32_t* Xp = Xpair + (t & 1) * XPAIRU;

        // A fragments: 8 LDS.32, zero cvts
        const uint32_t* xA = Xp + lg * XSTRIDE;
        const uint32_t* xB = xA + 8 * XSTRIDE;
        uint32_t a[8];
        a[0] = xA[lq];      a[1] = xB[lq];
        a[2] = xA[lq + 4];  a[3] = xB[lq + 4];
        a[4] = xA[lq + 8];  a[5] = xB[lq + 8];
        if (lq < 2) {
            a[6] = xA[lq + 12];
            a[7] = xB[lq + 12];
        } else if (lq == 2) {
            a[6] = (xA[14] & 0xFFFFu) | fb0aH;   // (x28, fb0)
            a[7] = (xB[14] & 0xFFFFu) | fb0bH;
        } else {
            a[6] = fb12a;                         // (fb1, fb2)
            a[7] = fb12b;
        }

        // prefetch this warp's share of X(t+1), packed at load time (off critical path)
        uint32_t xr[4];
        const bool pf = (t + 1) < T_HOR;
        if (pf) {
            const float* __restrict__ src = Xbase + (size_t)(t + 1) * F_IN;
            #pragma unroll
            for (int k = 0; k < 4; ++k) {
                if (lane + k * 32 < 120) {
                    const int j = jBase + lane + k * 32;
                    const int row = j / 15, p = j - row * 15;
                    const float lo = __ldg(src + (size_t)row * TF_STR + 2 * p);
                    const float hi = (p < 14) ? __ldg(src + (size_t)row * TF_STR + 2 * p + 1) : 0.0f;
                    xr[k] = h2u(lo, hi);
                }
            }
        }

        // dot accumulators (fp32, via dot-MMA); n=0 result lands in lq==0's dt0/dt2
        float dt0 = 0.0f, dt1 = 0.0f, dt2 = 0.0f, dt3 = 0.0f;

        #pragma unroll 2
        for (int ntp = 0; ntp < 16; ++ntp) {
            uint32_t hlo0, hhi0, hlo1, hhi1;
            #pragma unroll
            for (int e = 0; e < 2; ++e) {
                const int ntg = ntOfs + 2 * ntp + e;
                const uint32_t b1u = b1h[ntg * 4 + lq];
                const uint4 bv = B4[ntg * 32 + lane];
                uint32_t dlo = b1u, dhi = b1u;                       // bias-init (f16x2)
                MMA_F16A(dlo, dhi, a[0], a[1], a[2], a[3], bv.x, bv.y);
                MMA_F16A(dlo, dhi, a[4], a[5], a[6], a[7], bv.z, bv.w);
                const uint32_t hlo = tanh2(dlo);   // rows lg,   cols c0,c1
                const uint32_t hhi = tanh2(dhi);   // rows lg+8, cols c0,c1
                if (e == 0) { hlo0 = hlo; hhi0 = hhi; }
                else        { hlo1 = hlo; hhi1 = hhi; }
            }
            // dot-MMA: A = h tile, B = w2 in n=0 (lg==0 lanes), fp32 D accum
            uint32_t w0 = 0, w1 = 0;
            if (lg == 0) {
                const uint2 wv = w2sm[w2Base + ntp * 4 + lq];
                w0 = wv.x; w1 = wv.y;
            }
            MMA_F16(dt0, dt1, dt2, dt3, hlo0, hhi0, hlo1, hhi1, w0, w1);
        }

        // store staged X(t+1) into the other buffer (fenced by BAR below)
        if (pf) {
            uint32_t* __restrict__ Xn = Xpair + ((t + 1) & 1) * XPAIRU;
            #pragma unroll
            for (int k = 0; k < 4; ++k) {
                if (lane + k * 32 < 120) {
                    const int j = jBase + lane + k * 32;
                    const int row = j / 15, p = j - row * 15;
                    Xn[row * XSTRIDE + p] = xr[k];
                }
            }
        }

        // exchange half-dots with the paired warp
        float* pbuf = part + (t & 1) * 128;
        if (lq == 0) {
            pbuf[pBase + h * 16 + lg]     = dt0;   // rows lg
            pbuf[pBase + h * 16 + lg + 8] = dt2;   // rows lg+8
        }
        BAR_PAIR(barId);    // drains STS (partials AND X(t+1)); syncs only the pair

        const float predA = pbuf[pBase + lg]     + pbuf[pBase + 16 + lg]     + b2v;
        const float predB = pbuf[pBase + lg + 8] + pbuf[pBase + 16 + lg + 8] + b2v;
        if (h == 0 && lq == 0) {
            outA[t] = predA;
            outB[t] = predB;
        }
        // shift feedback: fb2 <- fb1 <- fb0 <- pred (repack)
        fb12a = (fb0aH >> 16) | (fb12a << 16);     // (fb0_old, fb1_old)
        fb12b = (fb0bH >> 16) | (fb12b << 16);
        fb0aH = h2u(0.0f, predA);
        fb0bH = h2u(0.0f, predB);
        f0a = predA; f0b = predB;                  // keep fp32 copies (unused but cheap)
    }
}

extern "C" void kernel_launch(void* const* d_in, const int* in_sizes, int n_in,
                              void* d_out, int out_size) {
    const float* X  = (const float*)d_in[0];
    const float* y0 = (const float*)d_in[1];
    const float* W1 = (const float*)d_in[2];
    const float* b1 = (const float*)d_in[3];
    const float* W2 = (const float*)d_in[4];
    const float* b2 = (const float*)d_in[5];
    float* out = (float*)d_out;
    (void)in_sizes; (void)n_in; (void)out_size;

    cudaFuncSetAttribute(narx_kernel, cudaFuncAttributeMaxDynamicSharedMemorySize, SM_TOTAL);
    narx_kernel<<<NCTAS, NTH, SM_TOTAL>>>(X, y0, W1, b1, W2, b2, out);
}